// round 11
// baseline (speedup 1.0000x reference)
#include <cuda_runtime.h>
#include <cuda_bf16.h>
#include <math.h>

// Problem constants
#define H_NF 128
#define N_GAUSS 50
#define MAX_NODES 100000

#define TPB 256
#define WPB (TPB / 32)
#define GRID_CTAS (148 * 4)     // all-resident persistent grid (regs <= 64)

// step = 10/49 ; exp(coeff*(d-o)^2) = 2^( -(A*d - A*o)^2 ), A = sqrt(0.5*log2e)/step
#define STEP_D    (10.0 / 49.0)
#define A_CONST   ((float)(0.8493255219056067 / STEP_D))
#define AS_CONST  ((float)0.8493255219056067)

// Padded coords scratch: [N] float4. Static device array (no alloc).
__device__ float4 g_coords4[MAX_NODES];

__global__ void pad_coords_kernel(const float* __restrict__ coords, int n_nodes) {
    int i = blockIdx.x * blockDim.x + threadIdx.x;
    if (i < n_nodes) {
        float4 v;
        v.x = __ldg(&coords[(size_t)i * 3 + 0]);
        v.y = __ldg(&coords[(size_t)i * 3 + 1]);
        v.z = __ldg(&coords[(size_t)i * 3 + 2]);
        v.w = 0.0f;
        g_coords4[i] = v;
    }
}

__device__ __forceinline__ float edge_dist(const float4& a, const float4& b) {
    float dx = a.x - b.x, dy = a.y - b.y, dz = a.z - b.z;
    return sqrtf(fmaf(dx, dx, fmaf(dy, dy, dz * dz)));
}

// One phase-2 step: writes one float4 (4 gaussians) per lane, advances state.
#define PHASE2_BODY                                                     \
    {                                                                   \
        int  half = le >> 1;                                            \
        bool odd  = (le & 1);                                           \
        float sA = __shfl_sync(0xffffffffu, r0, half);                  \
        float sB = __shfl_sync(0xffffffffu, r1, half);                  \
        float sC = __shfl_sync(0xffffffffu, r0, half + 1);              \
        float u  = odd ? sB : sA;                                       \
        float un = odd ? sC : sB;                                       \
        bool span = (g == 48);                                          \
        float og = (float)g * AS_CONST;                                 \
        float d0 = u - og;                                              \
        float d1 = d0 - AS_CONST;                                       \
        float d2 = span ? un : (d1 - AS_CONST);                         \
        float d3 = d2 - AS_CONST;                                       \
        float4 rr;                                                      \
        rr.x = exp2f(d0 * -d0);                                         \
        rr.y = exp2f(d1 * -d1);                                         \
        rr.z = exp2f(d2 * -d2);                                         \
        rr.w = exp2f(d3 * -d3);                                         \
        __stcs(&base4[idx], rr);                                        \
        idx += 32;                                                      \
        g += 28; le += 2;                                               \
        if (g >= 50) { g -= 50; le += 1; }                              \
    }

// ---------------------------------------------------------------------------
// Persistent fused kernel: node sweep + software-pipelined 64-edge tiles.
// ---------------------------------------------------------------------------
__global__ __launch_bounds__(TPB) void fused_kernel(
    const int*   __restrict__ atomic_ns,   // [N]
    const int*   __restrict__ edge_index,  // [2, E]
    const float4* __restrict__ weight4,    // [100, 32] as float4
    float4* __restrict__ out_node4,        // [N, 32] as float4
    float*  __restrict__ out_eembs,        // [E, 50]
    float*  __restrict__ out_ew,           // [E]
    long long n_edges,
    int n_nodes)
{
    const int tid  = threadIdx.x;
    const int w    = tid >> 5;
    const int lane = tid & 31;
    const int gw     = blockIdx.x * WPB + w;   // global warp id
    const int nwarps = gridDim.x * WPB;

    // ---------------- node-embedding sweep: 4-wide batched per warp --------
    for (long long base = (long long)gw * 4; base < n_nodes;
         base += (long long)nwarps * 4) {
        int cnt = (int)((n_nodes - base) < 4 ? (n_nodes - base) : 4);
        int a[4];
        #pragma unroll
        for (int k = 0; k < 4; ++k)
            if (k < cnt) a[k] = __ldg(&atomic_ns[base + k]);
        float4 wv[4];
        #pragma unroll
        for (int k = 0; k < 4; ++k)
            if (k < cnt) wv[k] = __ldg(&weight4[(size_t)a[k] * 32 + lane]);
        #pragma unroll
        for (int k = 0; k < 4; ++k)
            if (k < cnt) __stcs(&out_node4[(size_t)(base + k) * 32 + lane], wv[k]);
    }

    // ---------------- edge tiles: 64 edges per tile, pipelined -------------
    const long long n_tiles = n_edges >> 6;
    const bool even_E = ((n_edges & 1) == 0);
    const int2* __restrict__ ei2 = (const int2*)edge_index;

    long long t = gw;
    if (t < n_tiles) {
        // Prologue: load indices + gather + dist for first tile (exposed once).
        int2 iv, jv;
        iv = __ldcg(&ei2[(size_t)(t << 5) + lane]);
        if (even_E) {
            jv = __ldcg(&ei2[(size_t)((n_edges >> 1) + (t << 5)) + lane]);
        } else {
            long long e = (t << 6) + 2 * lane;
            jv.x = __ldcg(&edge_index[n_edges + e]);
            jv.y = __ldcg(&edge_index[n_edges + e + 1]);
        }
        float4 A0 = __ldcg(&g_coords4[iv.x]);
        float4 B0 = __ldcg(&g_coords4[jv.x]);
        float4 A1 = __ldcg(&g_coords4[iv.y]);
        float4 B1 = __ldcg(&g_coords4[jv.y]);
        float dist0 = edge_dist(A0, B0);
        float dist1 = edge_dist(A1, B1);
        {
            float2 dw; dw.x = dist0; dw.y = dist1;
            __stcs(&((float2*)out_ew)[(t << 5) + lane], dw);
        }
        float r0 = dist0 * A_CONST;
        float r1 = dist1 * A_CONST;

        for (;;) {
            long long tn = t + nwarps;
            bool hn = (tn < n_tiles);

            // (a) issue next tile's index loads immediately
            int2 ivn, jvn;
            if (hn) {
                ivn = __ldcg(&ei2[(size_t)(tn << 5) + lane]);
                if (even_E) {
                    jvn = __ldcg(&ei2[(size_t)((n_edges >> 1) + (tn << 5)) + lane]);
                } else {
                    long long e = (tn << 6) + 2 * lane;
                    jvn.x = __ldcg(&edge_index[n_edges + e]);
                    jvn.y = __ldcg(&edge_index[n_edges + e + 1]);
                }
            }

            // phase 2 for tile t: 25 float4 stores per lane, split 12 + 13
            float4* __restrict__ base4 =
                reinterpret_cast<float4*>(out_eembs + (t << 6) * N_GAUSS);
            int f  = 4 * lane;
            int le = f / 50;
            int g  = f - 50 * le;
            int idx = lane;
            #pragma unroll
            for (int it = 0; it < 12; ++it) PHASE2_BODY

            // (b) issue next tile's coord gathers (indices have landed by now)
            if (hn) {
                A0 = __ldcg(&g_coords4[ivn.x]);
                B0 = __ldcg(&g_coords4[jvn.x]);
                A1 = __ldcg(&g_coords4[ivn.y]);
                B1 = __ldcg(&g_coords4[jvn.y]);
            }

            #pragma unroll
            for (int it = 0; it < 13; ++it) PHASE2_BODY

            if (!hn) break;

            // (c) finish next tile's phase 1 (gathers landed during 13 iters)
            dist0 = edge_dist(A0, B0);
            dist1 = edge_dist(A1, B1);
            float2 dw; dw.x = dist0; dw.y = dist1;
            __stcs(&((float2*)out_ew)[(tn << 5) + lane], dw);
            r0 = dist0 * A_CONST;
            r1 = dist1 * A_CONST;
            t = tn;
        }
    }

    // ---------------- remainder edges (< 64): one warp, scalar path --------
    if (gw == 0) {
        for (long long e = (n_tiles << 6) + lane; e < n_edges; e += 32) {
            int i = __ldcg(&edge_index[e]);
            int j = __ldcg(&edge_index[n_edges + e]);
            float4 a = __ldcg(&g_coords4[i]);
            float4 b = __ldcg(&g_coords4[j]);
            float dist = edge_dist(a, b);
            out_ew[e] = dist;
            float rr = dist * A_CONST;
            #pragma unroll 10
            for (int gg = 0; gg < N_GAUSS; ++gg) {
                float d = rr - (float)gg * AS_CONST;
                out_eembs[e * N_GAUSS + gg] = exp2f(d * -d);
            }
        }
    }
}

// ---------------------------------------------------------------------------
// Inputs (metadata order):
//   0: atomic_ns int32 [N], 1: edge_index int32 [2,E], 2: coords f32 [N,3],
//   3: batch_node_vec int32 [N] (unused), 4: node_emb_weight f32 [100,128]
// Output (f32): node_embs [N,128] | edge_embs [E,50] | edge_weights [E]
// ---------------------------------------------------------------------------
extern "C" void kernel_launch(void* const* d_in, const int* in_sizes, int n_in,
                              void* d_out, int out_size) {
    const int*   atomic_ns  = (const int*)d_in[0];
    const int*   edge_index = (const int*)d_in[1];
    const float* coords     = (const float*)d_in[2];
    const float* weight     = (const float*)d_in[4];

    const int       n_nodes = in_sizes[0];
    const long long n_edges = (long long)in_sizes[1] / 2;

    float* out = (float*)d_out;
    float* out_node  = out;
    float* out_eembs = out + (size_t)n_nodes * H_NF;
    float* out_ew    = out_eembs + (size_t)n_edges * N_GAUSS;

    // Prologue: pad coords into float4 scratch
    {
        int tpb = 256;
        int blocks = (n_nodes + tpb - 1) / tpb;
        pad_coords_kernel<<<blocks, tpb>>>(coords, n_nodes);
    }

    fused_kernel<<<GRID_CTAS, TPB>>>(
        atomic_ns, edge_index,
        (const float4*)weight,
        (float4*)out_node, out_eembs, out_ew,
        n_edges, n_nodes);
}